// round 8
// baseline (speedup 1.0000x reference)
#include <cuda_runtime.h>
#include <cuda_bf16.h>
#include <cstddef>

// Fused YOLOv3 decode. Block-specialized single kernel:
//   blocks [0, pairBlocks)   : float2 path, scales 26 & 52, 2 cells/thread
//   blocks [pairBlocks, end) : scalar path, scale 13
// The branch is uniform per BLOCK (R4/R5 per-thread dual-path versions blew up
// to 124-128 regs; each path here is compiled lean under launch_bounds(256,5)).
// float2: pos and S both even -> the 2-cell pair never wraps a grid row.
// boxes rows are 24B (8B aligned) -> written as 3x STG.64.

__device__ __forceinline__ float sigf(float x) { return 1.0f / (1.0f + __expf(-x)); }

__global__ __launch_bounds__(256, 5)
void yolo_decode_r8(const float* __restrict__ o13,
                    const float* __restrict__ o26,
                    const float* __restrict__ o52,
                    const float* __restrict__ a13,
                    const float* __restrict__ a26,
                    const float* __restrict__ a52,
                    const float* __restrict__ threshp,
                    const int*   __restrict__ casep,
                    float* __restrict__ boxes,   // [N,6]
                    float* __restrict__ mask,    // [N]
                    int B, int pairBlocks)
{
    const int C13 = B * 13 * 13;
    const int C26 = B * 26 * 26;
    const int C52 = B * 52 * 52;
    const int P26 = C26 >> 1;
    const int P52 = C52 >> 1;

    const int iv = __ldg(casep);
    const float case_f = (iv > 0 && iv < 1000000) ? (float)iv : __int_as_float(iv);
    const float inv_case = 1.0f / case_f;
    const float thresh = __ldg(threshp);

    if (blockIdx.x < pairBlocks) {
        // ---------------- float2 pair path: scales 26 & 52 ----------------
        const int p = blockIdx.x * blockDim.x + threadIdx.x;
        const int npair = 3 * (P26 + P52);
        if (p >= npair) return;

        const float* in; const float* anch;
        int S, HW, Pc, q, rowoff; float t;
        if (p < 3 * P26) { in = o26; anch = a26; S = 26; HW = 676;  Pc = P26;
                           q = p;            rowoff = C13 * 3;         t = 16.0f; }
        else             { in = o52; anch = a52; S = 52; HW = 2704; Pc = P52;
                           q = p - 3 * P26;  rowoff = (C13 + C26) * 3; t = 8.0f;  }
        const float scale = t * inv_case;

        const int a     = q / Pc;
        const int pairi = q - a * Pc;
        const int local = pairi << 1;
        const int b     = local / HW;
        const int pos   = local - b * HW;      // even, pos+1 < HW

        const float* ptr = in + (size_t)(b * 255 + a * 85) * HW + pos;  // 8B aligned

        const float2 q0 = *(const float2*)(ptr);
        const float2 q1 = *(const float2*)(ptr + HW);
        const float2 q2 = *(const float2*)(ptr + 2 * HW);
        const float2 q3 = *(const float2*)(ptr + 3 * HW);
        const float2 q4 = *(const float2*)(ptr + 4 * HW);

        // argmax over 80 class channels for both cells, float2 batches of 8.
        // Strict '>' keeps FIRST max (jnp.argmax tie rule).
        float mx0 = -3.4e38f, mx1 = -3.4e38f;
        int   c0 = 0, c1 = 0;
        const float* pc = ptr + 5 * HW;
        #pragma unroll
        for (int d0 = 0; d0 < 80; d0 += 8) {
            float2 v[8];
            #pragma unroll
            for (int i = 0; i < 8; ++i)
                v[i] = *(const float2*)(pc + (d0 + i) * HW);
            #pragma unroll
            for (int i = 0; i < 8; ++i) {
                const int d = d0 + i;
                if (v[i].x > mx0) { mx0 = v[i].x; c0 = d; }
                if (v[i].y > mx1) { mx1 = v[i].y; c1 = d; }
            }
        }

        const float ax = __ldg(anch + a * 2 + 0);
        const float ay = __ldg(anch + a * 2 + 1);

        const int h0 = pos / S;
        const int w0 = pos - h0 * S;           // even -> w0+1 <= S-1, no wrap

        // cell 0
        {
            const int row = rowoff + local * 3 + a;
            float* r = boxes + (size_t)row * 6;
            *(float2*)(r)     = make_float2(sigf(q0.x), ((float)w0 + q1.x) * scale);
            *(float2*)(r + 2) = make_float2(((float)h0 + q2.x) * scale,
                                            ax * __expf(q3.x) * inv_case);
            *(float2*)(r + 4) = make_float2(ay * __expf(q4.x) * inv_case, (float)c0);
            mask[row] = (q0.x > thresh) ? 1.0f : 0.0f;
        }
        // cell 1
        {
            const int row = rowoff + (local + 1) * 3 + a;
            float* r = boxes + (size_t)row * 6;
            *(float2*)(r)     = make_float2(sigf(q0.y), ((float)(w0 + 1) + q1.y) * scale);
            *(float2*)(r + 2) = make_float2(((float)h0 + q2.y) * scale,
                                            ax * __expf(q3.y) * inv_case);
            *(float2*)(r + 4) = make_float2(ay * __expf(q4.y) * inv_case, (float)c1);
            mask[row] = (q0.y > thresh) ? 1.0f : 0.0f;
        }
    } else {
        // ---------------- scalar path: scale 13 ----------------
        const int idx = (blockIdx.x - pairBlocks) * blockDim.x + threadIdx.x;
        if (idx >= 3 * C13) return;

        const int a     = idx / C13;
        const int local = idx - a * C13;
        const int HW = 169, S = 13;
        const int b   = local / HW;
        const int pos = local - b * HW;
        const int h   = pos / S;
        const int w   = pos - h * S;
        const float scale = 32.0f * inv_case;

        const float* ptr = o13 + (size_t)(b * 255 + a * 85) * HW + pos;

        const float v0 = __ldg(ptr);
        const float v1 = __ldg(ptr + HW);
        const float v2 = __ldg(ptr + 2 * HW);
        const float v3 = __ldg(ptr + 3 * HW);
        const float v4 = __ldg(ptr + 4 * HW);

        float maxv = -3.4e38f; int cls = 0;
        const float* pc = ptr + 5 * HW;
        #pragma unroll
        for (int d0 = 0; d0 < 80; d0 += 10) {
            float v[10];
            #pragma unroll
            for (int i = 0; i < 10; ++i) v[i] = __ldg(pc + (d0 + i) * HW);
            #pragma unroll
            for (int i = 0; i < 10; ++i)
                if (v[i] > maxv) { maxv = v[i]; cls = d0 + i; }
        }

        const int row = local * 3 + a;
        float* r = boxes + (size_t)row * 6;
        *(float2*)(r)     = make_float2(sigf(v0), ((float)w + v1) * scale);
        *(float2*)(r + 2) = make_float2(((float)h + v2) * scale,
                                        __ldg(a13 + a * 2 + 0) * __expf(v3) * inv_case);
        *(float2*)(r + 4) = make_float2(__ldg(a13 + a * 2 + 1) * __expf(v4) * inv_case,
                                        (float)cls);
        mask[row] = (v0 > thresh) ? 1.0f : 0.0f;
    }
}

extern "C" void kernel_launch(void* const* d_in, const int* in_sizes, int n_in,
                              void* d_out, int out_size)
{
    const float* o13 = (const float*)d_in[0];
    const float* o26 = (const float*)d_in[1];
    const float* o52 = (const float*)d_in[2];
    const float* a13 = (const float*)d_in[3];
    const float* a26 = (const float*)d_in[4];
    const float* a52 = (const float*)d_in[5];
    const float* th  = (const float*)d_in[6];
    const int*   cs  = (const int*)  d_in[7];

    const int B = in_sizes[0] / (255 * 13 * 13);

    const int C13 = B * 13 * 13;
    const int C26 = B * 26 * 26;
    const int C52 = B * 52 * 52;
    const int N = (C13 + C26 + C52) * 3;

    float* boxes = (float*)d_out;                   // [N,6]
    float* mask  = (float*)d_out + (size_t)N * 6;   // [N]

    const int TPB = 256;
    const int npair = 3 * ((C26 >> 1) + (C52 >> 1));
    const int pairBlocks = (npair + TPB - 1) / TPB;
    const int s13Blocks  = (3 * C13 + TPB - 1) / TPB;

    yolo_decode_r8<<<pairBlocks + s13Blocks, TPB>>>(
        o13, o26, o52, a13, a26, a52, th, cs, boxes, mask, B, pairBlocks);
}